// round 13
// baseline (speedup 1.0000x reference)
#include <cuda_runtime.h>
#include <math.h>
#include <stdint.h>

#define D_IN   768
#define TWO_D  1536
#define Q_N    128
#define S_N    512
#define C_N    64
#define JCHUNKS 8
#define JPER   (TWO_D / JCHUNKS)    /* 192 */
#define KSPLIT 384
#define NCB    32                   /* chunk-blocks = JCHUNKS * 4 s-tiles */
#define NBLK   240

typedef unsigned long long ull;

// Scratch (device globals: allocation-free per harness rules)
__device__ float    v13_hq0[Q_N * TWO_D];
__device__ float    v13_hq1[Q_N * TWO_D];
__device__ float    v13_hs0[S_N * TWO_D];
__device__ float    v13_hs1[S_N * TWO_D];
__device__ double   v13_part2[NCB * Q_N * C_N];     // class-binned partials
__device__ double   v13_loss[Q_N];
__device__ unsigned v13_gdone = 0;                  // gemm-phase counter
__device__ unsigned v13_sdone = 0;                  // scores-phase counter
__device__ unsigned v13_ticket = 0;                 // agg final ticket

__device__ __forceinline__ float v13_tf32(float x) {
    unsigned u;
    asm("cvt.rna.tf32.f32 %0, %1;" : "=r"(u) : "f"(x));
    return __uint_as_float(u);
}

__device__ __forceinline__ void v13_mma(float d[4], const unsigned a[4], const unsigned b[2]) {
    asm volatile(
        "mma.sync.aligned.m16n8k8.row.col.f32.tf32.tf32.f32 "
        "{%0,%1,%2,%3}, {%4,%5,%6,%7}, {%8,%9}, {%0,%1,%2,%3};"
        : "+f"(d[0]), "+f"(d[1]), "+f"(d[2]), "+f"(d[3])
        : "r"(a[0]), "r"(a[1]), "r"(a[2]), "r"(a[3]), "r"(b[0]), "r"(b[1]));
}

#define V13_ADD2(d, a, b) \
    asm("add.rn.f32x2 %0, %1, %2;" : "=l"(d) : "l"(a), "l"(b))
#define V13_FMA2(acc, t, w) \
    asm("fma.rn.f32x2 %0, %1, %2, %0;" : "+l"(acc) : "l"(t), "l"(w))

__device__ __forceinline__ ull v13_relu2(ull t) {
    unsigned lo, hi;
    asm("mov.b64 {%0,%1}, %2;" : "=r"(lo), "=r"(hi) : "l"(t));
    int l2 = max((int)lo, 0);
    int h2 = max((int)hi, 0);
    ull r;
    asm("mov.b64 %0, {%1,%2};" : "=l"(r) : "r"((unsigned)l2), "r"((unsigned)h2));
    return r;
}

__device__ __forceinline__ unsigned v13_ldacq(const unsigned* p) {
    unsigned v;
    asm volatile("ld.acquire.gpu.u32 %0, [%1];" : "=r"(v) : "l"(p) : "memory");
    return v;
}

// ---------------------------------------------------------------------------
// Fused persistent kernel: gemm (240 blocks) -> grid sync -> scores+binning
// (blocks 0..127) -> grid sync -> per-query agg + ticket final.
// All 240 blocks co-resident (occ 2) => spin barriers are deadlock-free.
// ---------------------------------------------------------------------------
#define V13_ST     40
#define V13_ASZ    (2 * 64 * V13_ST)
#define V13_BSZ    (2 * 128 * V13_ST)
#define V13_SMEM   ((V13_ASZ + V13_BSZ) * 4)     /* 40960 B dynamic */

__global__ void __launch_bounds__(256, 2)
v13_fused(const float* __restrict__ query,
          const float* __restrict__ support,
          const float* __restrict__ W1,
          const float* __restrict__ b1,
          const float* __restrict__ W2,
          const float* __restrict__ b2,
          const int*   __restrict__ labels,
          const int*   __restrict__ targets,
          float* __restrict__ out, int out_size)
{
    extern __shared__ __align__(16) char dyn[];
    __shared__ int    sh_lab[S_N];
    __shared__ double sh_aggv[C_N];
    __shared__ double sh_redv[C_N];
    __shared__ int    sh_redi[C_N];
    __shared__ double sh_rede[C_N];
    __shared__ int    sh_isLast;
    __shared__ double sh_lred[Q_N];

    const int b   = blockIdx.x;
    const int tid = threadIdx.x;

    // ======================= PHASE 1: GEMM (all 240 blocks) =================
    {
        float* As = (float*)dyn;
        float* Bs = (float*)dyn + V13_ASZ;

        const int lane = tid & 31;
        const int wid  = tid >> 5;
        const int warpM = wid & 1;
        const int warpN = wid >> 1;
        const int g = lane >> 2;
        const int t = lane & 3;

        const int bx = b % 12;
        const int by = (b / 12) % 10;
        const int z  = b / 120;
        const int  kOff = z * KSPLIT;
        const bool isQ  = (by < 2);
        const float* Arow = isQ ? (query + (size_t)by * 64 * D_IN)
                                : (support + (size_t)(by - 2) * 64 * D_IN);
        const int   wOff  = (isQ ? 0 : D_IN) + kOff;
        const int   jBase = bx * 128;
        float* Hq = z ? v13_hq1 : v13_hq0;
        float* Hs = z ? v13_hs1 : v13_hs0;
        float* Crow = isQ ? (Hq + (size_t)by * 64 * TWO_D)
                          : (Hs + (size_t)(by - 2) * 64 * TWO_D);

        const int a_row = tid >> 2, a_ks = tid & 3;
        const int b_row0 = tid >> 2, b_ks0 = tid & 3;
        const int b_row1 = (tid + 256) >> 2, b_ks1 = tid & 3;
        const float* aSeg  = Arow + (size_t)a_row * D_IN + kOff + a_ks * 8;
        const float* bSeg0 = W1 + (size_t)(jBase + b_row0) * TWO_D + wOff + b_ks0 * 8;
        const float* bSeg1 = W1 + (size_t)(jBase + b_row1) * TWO_D + wOff + b_ks1 * 8;

        float4 pa0, pa1, pb00, pb01, pb10, pb11;
        #define V13_PREFETCH(kb) do {                                   \
            pa0  = *(const float4*)(aSeg  + (kb));                      \
            pa1  = *(const float4*)(aSeg  + (kb) + 4);                  \
            pb00 = *(const float4*)(bSeg0 + (kb));                      \
            pb01 = *(const float4*)(bSeg0 + (kb) + 4);                  \
            pb10 = *(const float4*)(bSeg1 + (kb));                      \
            pb11 = *(const float4*)(bSeg1 + (kb) + 4);                  \
        } while (0)

        #define V13_STAGE(buf) do {                                                     \
            float* ap = As + ((buf) * 64 + a_row) * V13_ST + a_ks * 8;                  \
            float2 p;                                                                   \
            p.x = v13_tf32(pa0.x); p.y = v13_tf32(pa1.x); *(float2*)(ap + 0) = p;       \
            p.x = v13_tf32(pa0.y); p.y = v13_tf32(pa1.y); *(float2*)(ap + 2) = p;       \
            p.x = v13_tf32(pa0.z); p.y = v13_tf32(pa1.z); *(float2*)(ap + 4) = p;       \
            p.x = v13_tf32(pa0.w); p.y = v13_tf32(pa1.w); *(float2*)(ap + 6) = p;       \
            float* bp = Bs + ((buf) * 128 + b_row0) * V13_ST + b_ks0 * 8;               \
            p.x = v13_tf32(pb00.x); p.y = v13_tf32(pb01.x); *(float2*)(bp + 0) = p;     \
            p.x = v13_tf32(pb00.y); p.y = v13_tf32(pb01.y); *(float2*)(bp + 2) = p;     \
            p.x = v13_tf32(pb00.z); p.y = v13_tf32(pb01.z); *(float2*)(bp + 4) = p;     \
            p.x = v13_tf32(pb00.w); p.y = v13_tf32(pb01.w); *(float2*)(bp + 6) = p;     \
            bp = Bs + ((buf) * 128 + b_row1) * V13_ST + b_ks1 * 8;                      \
            p.x = v13_tf32(pb10.x); p.y = v13_tf32(pb11.x); *(float2*)(bp + 0) = p;     \
            p.x = v13_tf32(pb10.y); p.y = v13_tf32(pb11.y); *(float2*)(bp + 2) = p;     \
            p.x = v13_tf32(pb10.z); p.y = v13_tf32(pb11.z); *(float2*)(bp + 4) = p;     \
            p.x = v13_tf32(pb10.w); p.y = v13_tf32(pb11.w); *(float2*)(bp + 6) = p;     \
        } while (0)

        float d[2][4][4] = {};

        V13_PREFETCH(0);
        V13_STAGE(0);
        V13_PREFETCH(32);

        for (int kt = 0; kt < 12; kt++) {
            const int buf = kt & 1;
            __syncthreads();
            if (kt < 11) {
                V13_STAGE(buf ^ 1);
                if (kt < 10) V13_PREFETCH((kt + 2) * 32);
            }

            const float* Ab = As + buf * 64 * V13_ST;
            const float* Bb = Bs + buf * 128 * V13_ST;
            #pragma unroll
            for (int s = 0; s < 4; s++) {
                unsigned afr[2][4];
                #pragma unroll
                for (int mf = 0; mf < 2; mf++) {
                    const int r0 = warpM * 32 + mf * 16 + g;
                    float2 p0 = *(const float2*)(Ab + r0 * V13_ST + s * 8 + t * 2);
                    float2 p1 = *(const float2*)(Ab + (r0 + 8) * V13_ST + s * 8 + t * 2);
                    afr[mf][0] = __float_as_uint(p0.x);
                    afr[mf][1] = __float_as_uint(p1.x);
                    afr[mf][2] = __float_as_uint(p0.y);
                    afr[mf][3] = __float_as_uint(p1.y);
                }
                #pragma unroll
                for (int nf = 0; nf < 4; nf++) {
                    const int n = warpN * 32 + nf * 8 + g;
                    float2 q = *(const float2*)(Bb + n * V13_ST + s * 8 + t * 2);
                    unsigned bfr[2] = { __float_as_uint(q.x), __float_as_uint(q.y) };
                    v13_mma(d[0][nf], afr[0], bfr);
                    v13_mma(d[1][nf], afr[1], bfr);
                }
            }
        }

        const bool addBias = isQ && (z == 0);
        #pragma unroll
        for (int mf = 0; mf < 2; mf++) {
            const int r0 = warpM * 32 + mf * 16 + g;
            #pragma unroll
            for (int nf = 0; nf < 4; nf++) {
                const int c0 = jBase + warpN * 32 + nf * 8 + t * 2;
                float2 bias = make_float2(0.f, 0.f);
                if (addBias) bias = *(const float2*)(b1 + c0);
                float2 v0 = make_float2(d[mf][nf][0] + bias.x, d[mf][nf][1] + bias.y);
                float2 v1 = make_float2(d[mf][nf][2] + bias.x, d[mf][nf][3] + bias.y);
                *(float2*)(Crow + (size_t)r0 * TWO_D + c0)       = v0;
                *(float2*)(Crow + (size_t)(r0 + 8) * TWO_D + c0) = v1;
            }
        }
    }

    // ---- grid barrier: gemm done ----
    __threadfence();
    __syncthreads();
    if (tid == 0) atomicAdd(&v13_gdone, 1u);
    if (b >= 128) return;
    if (tid == 0) {
        while (v13_ldacq(&v13_gdone) < (unsigned)NBLK) { }
    }
    __syncthreads();
    __threadfence();

    // ================ PHASE 2: scores + class binning (blocks 0..127) =======
    {
        float2* Aq2 = (float2*)(dyn);                 // [2][8][34]
        float2* Bs2 = (float2*)(dyn + 4352);          // [2][8][130]
        float2* ws2 = (float2*)(dyn + 20992);         // [2][8]
        double* scr  = (double*)(dyn);                // [32][129] (phase 2b overlay)
        int*    lab2 = (int*)(dyn + 33024);           // [128]
        int*    seg  = (int*)(dyn + 33536);           // [65]

        const int sx     = b & 3;
        const int qy     = (b >> 2) & 3;
        const int jc     = b >> 4;
        const int sBase  = sx * 128;
        const int qBase  = qy * 32;
        const int jcBase = jc * JPER;
        const int ty = tid >> 4;
        const int tx = tid & 15;

        const int aq_q  = tid >> 3;
        const int aq_jp = tid & 7;
        const size_t hqOff = (size_t)(qBase + aq_q) * TWO_D + jcBase + aq_jp * 2;
        const int bs_s  = tid >> 1;
        const int bs_h  = (tid & 1) * 8;
        const int bs_jp = bs_h >> 1;
        const size_t hsOff = (size_t)(sBase + bs_s) * TWO_D + jcBase + bs_h;

        float2 pa0, pa1, pw;
        float4 pb00, pb01, pb10, pb11;

        #define V13S_PRE(jt) do {                                          \
            pa0  = *(const float2*)(v13_hq0 + hqOff + (jt));               \
            pa1  = *(const float2*)(v13_hq1 + hqOff + (jt));               \
            pb00 = *(const float4*)(v13_hs0 + hsOff + (jt));               \
            pb01 = *(const float4*)(v13_hs0 + hsOff + (jt) + 4);           \
            pb10 = *(const float4*)(v13_hs1 + hsOff + (jt));               \
            pb11 = *(const float4*)(v13_hs1 + hsOff + (jt) + 4);           \
            if (tid < 8) pw = *(const float2*)(W2 + jcBase + (jt) + tid * 2); \
        } while (0)

        #define V13S_STAGE(buf) do {                                                            \
            Aq2[(buf)*272 + aq_jp*34 + aq_q] = make_float2(pa0.x + pa1.x, pa0.y + pa1.y);       \
            Bs2[(buf)*1040 + (bs_jp+0)*130 + bs_s] = make_float2(pb00.x + pb10.x, pb00.y + pb10.y); \
            Bs2[(buf)*1040 + (bs_jp+1)*130 + bs_s] = make_float2(pb00.z + pb10.z, pb00.w + pb10.w); \
            Bs2[(buf)*1040 + (bs_jp+2)*130 + bs_s] = make_float2(pb01.x + pb11.x, pb01.y + pb11.y); \
            Bs2[(buf)*1040 + (bs_jp+3)*130 + bs_s] = make_float2(pb01.z + pb11.z, pb01.w + pb11.w); \
            if (tid < 8) ws2[(buf)*8 + tid] = pw;                                               \
        } while (0)

        ull acc2[2][8] = {};

        V13S_PRE(0);
        __syncthreads();     // gemm smem reads fully retired before overlay write
        V13S_STAGE(0);
        V13S_PRE(16);

        for (int it = 0; it < 12; it++) {
            const int buf = it & 1;
            __syncthreads();
            if (it < 11) {
                V13S_STAGE(buf ^ 1);
                if (it < 10) V13S_PRE((it + 2) * 16);
            }

            #pragma unroll
            for (int jp = 0; jp < 8; jp++) {
                const ull w2v = *(const ull*)&ws2[buf*8 + jp];
                const ull a0  = *(const ull*)&Aq2[buf*272 + jp*34 + ty*2];
                const ull a1  = *(const ull*)&Aq2[buf*272 + jp*34 + ty*2 + 1];
                #pragma unroll
                for (int l = 0; l < 8; l++) {
                    const ull bv = *(const ull*)&Bs2[buf*1040 + jp*130 + tx + l*16];
                    ull t0; V13_ADD2(t0, a0, bv);
                    t0 = v13_relu2(t0);
                    V13_FMA2(acc2[0][l], t0, w2v);
                    ull t1; V13_ADD2(t1, a1, bv);
                    t1 = v13_relu2(t1);
                    V13_FMA2(acc2[1][l], t1, w2v);
                }
            }
        }

        __syncthreads();   // staging reads done before fp64 overlay

        #pragma unroll
        for (int i = 0; i < 2; i++)
            #pragma unroll
            for (int l = 0; l < 8; l++) {
                unsigned lo, hi;
                asm("mov.b64 {%0,%1}, %2;" : "=r"(lo), "=r"(hi) : "l"(acc2[i][l]));
                scr[(ty*2 + i) * 129 + tx + l*16] =
                    (double)(__uint_as_float(lo) + __uint_as_float(hi));
            }
        if (tid < 128) lab2[tid] = labels[sBase + tid];
        __syncthreads();

        if (tid <= 64) {
            const int c = tid;
            int lo = 0, hi = 128;
            while (lo < hi) { int m = (lo + hi) >> 1; if (lab2[m] < c) lo = m + 1; else hi = m; }
            seg[tid] = lo;
        }
        __syncthreads();

        const int cb = jc * 4 + sx;
        double* outp = v13_part2 + ((size_t)cb * Q_N + qBase) * C_N;
        #pragma unroll
        for (int k = 0; k < 8; k++) {
            const int p  = tid + k * 256;
            const int qq = p >> 6;
            const int cc = p & 63;
            double ssum = 0.0;
            const int s0 = seg[cc], s1 = seg[cc + 1];
            for (int s = s0; s < s1; s++) ssum += scr[qq * 129 + s];
            outp[p] = ssum;
        }
    }

    // ---- grid barrier: scores done ----
    __threadfence();
    __syncthreads();
    if (tid == 0) {
        atomicAdd(&v13_sdone, 1u);
        while (v13_ldacq(&v13_sdone) < 128u) { }
    }
    __syncthreads();
    __threadfence();

    // ================ PHASE 3: per-query aggregate (blocks 0..127) ==========
    {
        const int q = b;

        for (int i = tid; i < S_N; i += 256) sh_lab[i] = labels[i];
        __syncthreads();

        if (tid < C_N) {
            const double* P = v13_part2 + (size_t)q * C_N + tid;
            double s0 = 0.0, s1 = 0.0, s2 = 0.0, s3 = 0.0;
            #pragma unroll
            for (int cb = 0; cb < NCB; cb += 4) {
                s0 += P[(size_t)(cb + 0) * (Q_N * C_N)];
                s1 += P[(size_t)(cb + 1) * (Q_N * C_N)];
                s2 += P[(size_t)(cb + 2) * (Q_N * C_N)];
                s3 += P[(size_t)(cb + 3) * (Q_N * C_N)];
            }
            const double tot = (s0 + s1) + (s2 + s3);

            const int c = tid;
            int lo = 0, hi = S_N;
            while (lo < hi) { int m = (lo + hi) >> 1; if (sh_lab[m] < c) lo = m + 1; else hi = m; }
            int lo2 = lo, hi2 = S_N;
            while (lo2 < hi2) { int m = (lo2 + hi2) >> 1; if (sh_lab[m] < c + 1) lo2 = m + 1; else hi2 = m; }
            const int cnt = lo2 - lo;

            sh_aggv[tid] = tot / (double)(cnt > 1 ? cnt : 1) + (double)b2[0];
            sh_redv[tid] = sh_aggv[tid];
            sh_redi[tid] = tid;
        }
        __syncthreads();

        #pragma unroll
        for (int off = C_N / 2; off > 0; off >>= 1) {
            if (tid < off) {
                if (sh_redv[tid + off] > sh_redv[tid] ||
                    (sh_redv[tid + off] == sh_redv[tid] && sh_redi[tid + off] < sh_redi[tid])) {
                    sh_redv[tid] = sh_redv[tid + off];
                    sh_redi[tid] = sh_redi[tid + off];
                }
            }
            __syncthreads();
        }
        const double mx = sh_redv[0];
        const int    am = sh_redi[0];

        if (tid < C_N) sh_rede[tid] = exp(sh_aggv[tid] - mx);
        __syncthreads();
        #pragma unroll
        for (int off = C_N / 2; off > 0; off >>= 1) {
            if (tid < off) sh_rede[tid] += sh_rede[tid + off];
            __syncthreads();
        }

        if (tid == 0) {
            const int tgt = targets[q];
            const double logp = sh_aggv[tgt] - mx - log(sh_rede[0]);
            v13_loss[q] = -logp;
            if (1 + q < out_size) out[1 + q] = (am == tgt) ? 1.0f : 0.0f;
            __threadfence();
            unsigned tk = atomicAdd(&v13_ticket, 1u);
            sh_isLast = (tk == (unsigned)(Q_N - 1));
        }
        __syncthreads();

        if (sh_isLast) {
            __threadfence();
            if (tid < Q_N) sh_lred[tid] = v13_loss[tid];
            __syncthreads();
            #pragma unroll
            for (int off = Q_N / 2; off > 0; off >>= 1) {
                if (tid < off) sh_lred[tid] += sh_lred[tid + off];
                __syncthreads();
            }
            if (tid == 0) {
                if (out_size > 0) out[0] = (float)(sh_lred[0] / (double)Q_N);
                v13_ticket = 0;          // reset for next graph replay
                v13_sdone  = 0;
                v13_gdone  = 0;
            }
        }
    }
}

// ---------------------------------------------------------------------------
extern "C" void kernel_launch(void* const* d_in, const int* in_sizes, int n_in,
                              void* d_out, int out_size)
{
    const float* query   = (const float*)d_in[0];
    const float* support = (const float*)d_in[1];
    const float* W1      = (const float*)d_in[2];
    const float* b1      = (const float*)d_in[3];
    const float* W2      = (const float*)d_in[4];
    const float* b2      = (const float*)d_in[5];
    const int*   labels  = (const int*)  d_in[6];
    const int*   targets = (const int*)  d_in[7];
    (void)in_sizes; (void)n_in;

    float* out = (float*)d_out;

    cudaFuncSetAttribute(v13_fused, cudaFuncAttributeMaxDynamicSharedMemorySize, V13_SMEM);

    v13_fused<<<NBLK, 256, V13_SMEM>>>(query, support, W1, b1, W2, b2,
                                       labels, targets, out, out_size);
}